// round 11
// baseline (speedup 1.0000x reference)
#include <cuda_runtime.h>
#include <math.h>
#include <stdint.h>
#include <stddef.h>

#define NT    768
#define NH    12
#define DIM   384
#define PD    128
#define FEAT  2112
#define NPROJ 1152
#define NTILE 24
#define SPLITK 6

#define SCALAR_SCALE 0.14433756729740643f
#define POINT_SCALE  0.13608276348795434f
#define PAIR_SCALE   0.57735026918962584f

// ------------- device scratch -------------
__device__ __align__(16) float g_wall [DIM * NPROJ];
__device__ __align__(16) float g_proj [NT * NPROJ];
__device__ __align__(16) float g_qs   [NH * NT * 16];
__device__ __align__(16) float g_ks   [NH * NT * 16];
__device__ __align__(16) float g_vs   [NH * NT * 16];
__device__ __align__(16) float g_qpg  [NH * NT * 12];
__device__ __align__(16) float g_kpg  [NH * NT * 12];
__device__ __align__(16) float g_vpg  [NH * NT * 24];
__device__ __align__(16) float g_feats[(size_t)NT * FEAT];
__device__ __align__(16) float g_part [SPLITK * NT * DIM];

// ------------- pack weights -------------
__global__ __launch_bounds__(256) void pack_w(
    const float* __restrict__ Wq,  const float* __restrict__ Wk,
    const float* __restrict__ Wv,  const float* __restrict__ Wpq,
    const float* __restrict__ Wpk, const float* __restrict__ Wpv)
{
    int e = blockIdx.x * 256 + threadIdx.x;
    if (e >= DIM * NPROJ) return;
    int r = e / NPROJ, c = e % NPROJ;
    float v;
    if      (c < 192) v = Wq [r*192 + c];
    else if (c < 384) v = Wk [r*192 + (c-192)];
    else if (c < 576) v = Wv [r*192 + (c-384)];
    else if (c < 720) v = Wpq[r*144 + (c-576)];
    else if (c < 864) v = Wpk[r*144 + (c-720)];
    else              v = Wpv[r*288 + (c-864)];
    g_wall[e] = v;
}

// ------------- split-K SGEMM: 64x64 tile, TM=8 TN=4, 128 threads ----------
__global__ __launch_bounds__(128) void sgemm_sk(
    const float* __restrict__ A, const float* __restrict__ B,
    float* __restrict__ C, int M, int N, int K)
{
    __shared__ float As[16][64];
    __shared__ float Bs[16][68];
    const int tid = threadIdx.x;
    const int tx = tid & 15, ty = tid >> 4;
    const int row0 = blockIdx.y * 64, col0 = blockIdx.x * 64;
    const int kchunk = K / gridDim.z;
    const int kbeg = blockIdx.z * kchunk;

    float acc[8][4];
#pragma unroll
    for (int m = 0; m < 8; m++)
#pragma unroll
        for (int n = 0; n < 4; n++) acc[m][n] = 0.f;

    for (int k0 = kbeg; k0 < kbeg + kchunk; k0 += 16) {
        for (int e = tid; e < 256; e += 128) {
            int r = e >> 2, c4 = e & 3;
            float4 v = *reinterpret_cast<const float4*>(
                &A[(size_t)(row0+r)*K + k0 + c4*4]);
            As[c4*4+0][r] = v.x; As[c4*4+1][r] = v.y;
            As[c4*4+2][r] = v.z; As[c4*4+3][r] = v.w;
        }
        for (int e = tid; e < 256; e += 128) {
            int r = e >> 4, c4 = e & 15;
            *reinterpret_cast<float4*>(&Bs[r][c4*4]) =
                *reinterpret_cast<const float4*>(
                    &B[(size_t)(k0+r)*N + col0 + c4*4]);
        }
        __syncthreads();
#pragma unroll
        for (int kk = 0; kk < 16; kk++) {
            float a[8];
#pragma unroll
            for (int m = 0; m < 8; m++) a[m] = As[kk][ty*8 + m];
            float4 b = *reinterpret_cast<const float4*>(&Bs[kk][tx*4]);
#pragma unroll
            for (int m = 0; m < 8; m++) {
                acc[m][0] += a[m]*b.x; acc[m][1] += a[m]*b.y;
                acc[m][2] += a[m]*b.z; acc[m][3] += a[m]*b.w;
            }
        }
        __syncthreads();
    }
    float* Cz = C + (size_t)blockIdx.z * M * N;
#pragma unroll
    for (int m = 0; m < 8; m++) {
        int r = row0 + ty*8 + m;
        float4 v = make_float4(acc[m][0], acc[m][1], acc[m][2], acc[m][3]);
        *reinterpret_cast<float4*>(&Cz[(size_t)r*N + col0 + tx*4]) = v;
    }
}

// ------------- split-K reduce (+ output bias) -------------
__global__ __launch_bounds__(256) void reduce_k(
    float* __restrict__ out, const float* __restrict__ bout)
{
    int e = blockIdx.x * 256 + threadIdx.x;
    if (e >= NT * DIM) return;
    float s = 0.f;
#pragma unroll
    for (int z = 0; z < SPLITK; z++) s += g_part[(size_t)z*NT*DIM + e];
    out[e] = s + bout[e % DIM];
}

// ------------- relayout + rotate points to global frame -------------
__global__ __launch_bounds__(128) void relayout(
    const float* __restrict__ rot, const float* __restrict__ trans)
{
    const int i = blockIdx.x, t = threadIdx.x;
    __shared__ float R[9], tv[3];
    if (t < 9) R[t]  = rot[i*9 + t];
    if (t < 3) tv[t] = trans[i*3 + t];
    __syncthreads();
    const float* pr = g_proj + (size_t)i * NPROJ;
    for (int e = t; e < NH*16; e += 128) {
        int h = e/16, d = e%16;
        g_qs[((size_t)h*NT+i)*16+d] = pr[      h*16+d];
        g_ks[((size_t)h*NT+i)*16+d] = pr[192 + h*16+d];
        g_vs[((size_t)h*NT+i)*16+d] = pr[384 + h*16+d];
    }
    for (int e = t; e < NH*4; e += 128) {
        int h = e/4, p = e%4;
        const float* s = pr + 576 + h*12 + p*3;
        float x=s[0], y=s[1], z=s[2];
        float* o = g_qpg + ((size_t)h*NT+i)*12 + p*3;
        o[0]=R[0]*x+R[1]*y+R[2]*z+tv[0];
        o[1]=R[3]*x+R[4]*y+R[5]*z+tv[1];
        o[2]=R[6]*x+R[7]*y+R[8]*z+tv[2];
        s = pr + 720 + h*12 + p*3; x=s[0]; y=s[1]; z=s[2];
        o = g_kpg + ((size_t)h*NT+i)*12 + p*3;
        o[0]=R[0]*x+R[1]*y+R[2]*z+tv[0];
        o[1]=R[3]*x+R[4]*y+R[5]*z+tv[1];
        o[2]=R[6]*x+R[7]*y+R[8]*z+tv[2];
    }
    for (int e = t; e < NH*8; e += 128) {
        int h = e/8, p = e%8;
        const float* s = pr + 864 + h*24 + p*3;
        float x=s[0], y=s[1], z=s[2];
        float* o = g_vpg + ((size_t)h*NT+i)*24 + p*3;
        o[0]=R[0]*x+R[1]*y+R[2]*z+tv[0];
        o[1]=R[3]*x+R[4]*y+R[5]*z+tv[1];
        o[2]=R[6]*x+R[7]*y+R[8]*z+tv[2];
    }
}

// ------------- fused attention + pair-bias (TI=1, high occupancy) ---------
#define PRS_OFF 0          // [32][132]
#define ACC_OFF 4224       // [12][44]  scalar[0:16) pts[16:40)
#define PPS_OFF 4752       // [12][33]
#define BT2_OFF 5148       // [12][33]
#define QSS_OFF 5544       // [12][16]
#define QPS_OFF 5736       // [12][12]
#define WT_OFF  5880       // [12][132]
#define BB_OFF  7464       // [12]
#define MST_OFF 7476
#define LST_OFF 7488
#define FAC_OFF 7500
#define RS_OFF  7512
#define TV_OFF  7521
#define SMEM_FLOATS 7524

__global__ __launch_bounds__(384, 3) void attn_k(
    const float* __restrict__ pair, const float* __restrict__ rot,
    const float* __restrict__ trans, const float* __restrict__ pwts,
    const float* __restrict__ Wpb, const float* __restrict__ bpb)
{
    extern __shared__ float sm[];
    float* prs  = sm + PRS_OFF;
    float* accs = sm + ACC_OFF;
    float* pps  = sm + PPS_OFF;
    float* bts  = sm + BT2_OFF;
    float* qss  = sm + QSS_OFF;
    float* qps  = sm + QPS_OFF;
    float* wTs  = sm + WT_OFF;
    float* bbs  = sm + BB_OFF;
    float* mst  = sm + MST_OFF;
    float* lst  = sm + LST_OFF;
    float* facs = sm + FAC_OFF;
    float* Rs   = sm + RS_OFF;
    float* tvs  = sm + TV_OFF;

    const int i = blockIdx.x;
    const int t = threadIdx.x;
    const int h = t >> 5, lane = t & 31;

    // V roles: 120 threads, thread = (head hh2, float4-col c2)
    const bool has_sp = (t < 120);
    const int hh2 = t / 10, c2 = t % 10;
    const float* vbase;
    int vstride;
    if (c2 < 4) { vbase = g_vs  + (size_t)hh2*NT*16 + c2*4;     vstride = 16; }
    else        { vbase = g_vpg + (size_t)hh2*NT*24 + (c2-4)*4; vstride = 24; }

    // bias roles: 96 threads = 3 warps; warp wg -> heads 4wg..4wg+3, lane = row
    const int bwg = t >> 5;   // valid for t < 96

    float4 pacc = make_float4(0.f,0.f,0.f,0.f);   // pair acc: head h, col lane
    float4 spacc = make_float4(0.f,0.f,0.f,0.f);

    for (int e = t; e < NH*16; e += 384)
        qss[e] = g_qs[((size_t)(e/16)*NT + i)*16 + e%16];
    for (int e = t; e < NH*12; e += 384)
        qps[e] = g_qpg[((size_t)(e/12)*NT + i)*12 + e%12];
    for (int e = t; e < NH*PD; e += 384)
        wTs[(e >> 7)*132 + (e & 127)] = Wpb[(e & 127)*12 + (e >> 7)];
    if (t < NH) { bbs[t] = bpb[t]; mst[t] = -1e30f; lst[t] = 0.f; }
    if (t < 9) Rs[t]  = rot[i*9 + t];
    if (t < 3) tvs[t] = trans[i*3 + t];
    __syncthreads();

    float wv = pwts[h];
    float pwh = (wv > 20.f) ? wv : log1pf(expf(wv));
    const float pscale = -0.5f * POINT_SCALE * pwh;

    for (int jt = 0; jt < NTILE; jt++) {
        const int j0 = jt * 32;
        // ---- stage pair tile 32x128 (1024 float4, coalesced) ----
        for (int e = t; e < 1024; e += 384) {
            int r = e >> 5, c = e & 31;
            float4 v = *reinterpret_cast<const float4*>(
                pair + ((size_t)i*NT + j0 + r)*PD + c*4);
            *reinterpret_cast<float4*>(&prs[r*132 + c*4]) = v;
        }
        __syncthreads();
        // ---- K loads early: latency overlaps bias compute ----
        const int j = j0 + lane;
        const float4* krp = reinterpret_cast<const float4*>(g_ks  + ((size_t)h*NT + j)*16);
        const float4* kpp = reinterpret_cast<const float4*>(g_kpg + ((size_t)h*NT + j)*12);
        float4 k0 = krp[0], k1 = krp[1], k2 = krp[2], k3 = krp[3];
        float4 p0 = kpp[0], p1 = kpp[1], p2 = kpp[2];
        // ---- pair-bias: 3 warps, thread = row(lane) x 4 heads ----
        if (t < 96) {
            const float* w0 = wTs + (4*bwg+0)*132;
            const float* w1 = wTs + (4*bwg+1)*132;
            const float* w2 = wTs + (4*bwg+2)*132;
            const float* w3 = wTs + (4*bwg+3)*132;
            const float* prow = prs + lane*132;
            float b0 = 0.f, b1 = 0.f, b2 = 0.f, b3 = 0.f;
#pragma unroll 4
            for (int k4 = 0; k4 < 32; k4++) {
                float4 v  = *reinterpret_cast<const float4*>(prow + k4*4);
                float4 wa = *reinterpret_cast<const float4*>(w0 + k4*4);
                float4 wb = *reinterpret_cast<const float4*>(w1 + k4*4);
                float4 wc = *reinterpret_cast<const float4*>(w2 + k4*4);
                float4 wd = *reinterpret_cast<const float4*>(w3 + k4*4);
                b0 += v.x*wa.x + v.y*wa.y + v.z*wa.z + v.w*wa.w;
                b1 += v.x*wb.x + v.y*wb.y + v.z*wb.z + v.w*wb.w;
                b2 += v.x*wc.x + v.y*wc.y + v.z*wc.z + v.w*wc.w;
                b3 += v.x*wd.x + v.y*wd.y + v.z*wd.z + v.w*wd.w;
            }
            bts[(4*bwg+0)*33 + lane] = (b0 + bbs[4*bwg+0]) * PAIR_SCALE;
            bts[(4*bwg+1)*33 + lane] = (b1 + bbs[4*bwg+1]) * PAIR_SCALE;
            bts[(4*bwg+2)*33 + lane] = (b2 + bbs[4*bwg+2]) * PAIR_SCALE;
            bts[(4*bwg+3)*33 + lane] = (b3 + bbs[4*bwg+3]) * PAIR_SCALE;
        }
        __syncthreads();
        // ---- logits + online softmax (warp h, lane = j) ----
        {
            const float4* qsv = reinterpret_cast<const float4*>(qss + h*16);
            const float4* qpv = reinterpret_cast<const float4*>(qps + h*12);
            float4 a0 = qsv[0], a1 = qsv[1], a2 = qsv[2], a3 = qsv[3];
            float s = a0.x*k0.x + a0.y*k0.y + a0.z*k0.z + a0.w*k0.w
                    + a1.x*k1.x + a1.y*k1.y + a1.z*k1.z + a1.w*k1.w
                    + a2.x*k2.x + a2.y*k2.y + a2.z*k2.z + a2.w*k2.w
                    + a3.x*k3.x + a3.y*k3.y + a3.z*k3.z + a3.w*k3.w;
            s *= SCALAR_SCALE;
            float4 b0 = qpv[0], b1 = qpv[1], b2 = qpv[2];
            float dx, dist = 0.f;
            dx = b0.x-p0.x; dist += dx*dx; dx = b0.y-p0.y; dist += dx*dx;
            dx = b0.z-p0.z; dist += dx*dx; dx = b0.w-p0.w; dist += dx*dx;
            dx = b1.x-p1.x; dist += dx*dx; dx = b1.y-p1.y; dist += dx*dx;
            dx = b1.z-p1.z; dist += dx*dx; dx = b1.w-p1.w; dist += dx*dx;
            dx = b2.x-p2.x; dist += dx*dx; dx = b2.y-p2.y; dist += dx*dx;
            dx = b2.z-p2.z; dist += dx*dx; dx = b2.w-p2.w; dist += dx*dx;
            s += pscale * dist;
            s += bts[h*33 + lane];

            float mx = s;
#pragma unroll
            for (int o = 16; o; o >>= 1)
                mx = fmaxf(mx, __shfl_xor_sync(~0u, mx, o));
            float m_old = mst[h];
            float m_new = fmaxf(m_old, mx);
            float p = __expf(s - m_new);
            pps[h*33 + lane] = p;
            float ps = p;
#pragma unroll
            for (int o = 16; o; o >>= 1)
                ps += __shfl_xor_sync(~0u, ps, o);
            if (lane == 0) {
                float f = __expf(m_old - m_new);
                facs[h] = f;
                lst[h] = lst[h]*f + ps;
                mst[h] = m_new;
            }
        }
        __syncthreads();
        // ---- pair accumulate: thread = (head h, float4-col lane) ----
        {
            float f = facs[h];
            pacc.x *= f; pacc.y *= f; pacc.z *= f; pacc.w *= f;
            const float* pph = pps + h*33;
            const float* prow = prs + lane*4;
#pragma unroll 8
            for (int jj = 0; jj < 32; jj++) {
                float4 v = *reinterpret_cast<const float4*>(prow + jj*132);
                float p = pph[jj];
                pacc.x += p*v.x; pacc.y += p*v.y; pacc.z += p*v.z; pacc.w += p*v.w;
            }
        }
        // ---- scalar/point accumulate (120 threads) ----
        if (has_sp) {
            float f = facs[hh2];
            spacc.x *= f; spacc.y *= f; spacc.z *= f; spacc.w *= f;
            const float* pph = pps + hh2*33;
            const float* src = vbase + (size_t)j0*vstride;
#pragma unroll 8
            for (int jv = 0; jv < 32; jv++) {
                float p = pph[jv];
                float4 v = *reinterpret_cast<const float4*>(src + (size_t)jv*vstride);
                spacc.x += p*v.x; spacc.y += p*v.y; spacc.z += p*v.z; spacc.w += p*v.w;
            }
        }
        __syncthreads();
    }

    // ---- write scalar/point accs to smem, then finalize ----
    if (has_sp) {
        int off = (c2 < 4) ? c2*4 : 16 + (c2-4)*4;
        *reinterpret_cast<float4*>(accs + hh2*44 + off) = spacc;
    }
    __syncthreads();

    float* fo = g_feats + (size_t)i * FEAT;
    // pair output direct from registers
    {
        float inv = 1.f / lst[h];
        float4 r = make_float4(pacc.x*inv, pacc.y*inv, pacc.z*inv, pacc.w*inv);
        *reinterpret_cast<float4*>(fo + 576 + h*PD + lane*4) = r;
    }
    // scalar
    if (t < 192) {
        int hh = t >> 4, d = t & 15;
        fo[hh*16 + d] = accs[hh*44 + d] / lst[hh];
    }
    // points + norms
    if (t >= 192 && t < 288) {
        int u = t - 192;
        int hh = u >> 3, p = u & 7;
        float inv = 1.f / lst[hh];
        const float* ac = accs + hh*44 + 16 + p*3;
        float gx = ac[0]*inv - tvs[0];
        float gy = ac[1]*inv - tvs[1];
        float gz = ac[2]*inv - tvs[2];
        float lx = Rs[0]*gx + Rs[3]*gy + Rs[6]*gz;
        float ly = Rs[1]*gx + Rs[4]*gy + Rs[7]*gz;
        float lz = Rs[2]*gx + Rs[5]*gy + Rs[8]*gz;
        fo[192 + hh*24 + p*3 + 0] = lx;
        fo[192 + hh*24 + p*3 + 1] = ly;
        fo[192 + hh*24 + p*3 + 2] = lz;
        fo[480 + hh*8 + p] = sqrtf(lx*lx + ly*ly + lz*lz + 1e-8f);
    }
}

// ------------- launch -------------
extern "C" void kernel_launch(void* const* d_in, const int* in_sizes, int n_in,
                              void* d_out, int out_size)
{
    (void)in_sizes; (void)n_in; (void)out_size;
    const float* x     = (const float*)d_in[0];
    const float* pair  = (const float*)d_in[1];
    const float* rot   = (const float*)d_in[2];
    const float* trans = (const float*)d_in[3];
    const float* Wq    = (const float*)d_in[4];
    const float* Wk    = (const float*)d_in[5];
    const float* Wv    = (const float*)d_in[6];
    const float* Wpq   = (const float*)d_in[7];
    const float* Wpk   = (const float*)d_in[8];
    const float* Wpv   = (const float*)d_in[9];
    const float* Wpb   = (const float*)d_in[10];
    const float* bpb   = (const float*)d_in[11];
    const float* pwts  = (const float*)d_in[12];
    const float* Wout  = (const float*)d_in[13];
    const float* bout  = (const float*)d_in[14];
    float* out = (float*)d_out;

    void *p_wall, *p_proj, *p_feats, *p_part;
    cudaGetSymbolAddress(&p_wall,  g_wall);
    cudaGetSymbolAddress(&p_proj,  g_proj);
    cudaGetSymbolAddress(&p_feats, g_feats);
    cudaGetSymbolAddress(&p_part,  g_part);

    pack_w<<<(DIM*NPROJ + 255)/256, 256>>>(Wq, Wk, Wv, Wpq, Wpk, Wpv);
    {
        dim3 g(NPROJ/64, NT/64, 1);
        sgemm_sk<<<g, 128>>>(x, (const float*)p_wall, (float*)p_proj,
                             NT, NPROJ, DIM);
    }
    relayout<<<NT, 128>>>(rot, trans);
    attn_k<<<NT, 384, SMEM_FLOATS*4>>>(pair, rot, trans, pwts, Wpb, bpb);
    {
        dim3 g(DIM/64, NT/64, SPLITK);
        sgemm_sk<<<g, 128>>>((const float*)p_feats, Wout, (float*)p_part,
                             NT, DIM, FEAT);
    }
    reduce_k<<<(NT*DIM + 255)/256, 256>>>(out, bout);
}

// round 12
// speedup vs baseline: 1.6566x; 1.6566x over previous
#include <cuda_runtime.h>
#include <math.h>
#include <stdint.h>
#include <stddef.h>

#define NT    768
#define NH    12
#define DIM   384
#define PD    128
#define FEAT  2112
#define NPROJ 1152
#define TI    3
#define NTILE 24
#define SPLITK 6

#define SCALAR_SCALE 0.14433756729740643f
#define POINT_SCALE  0.13608276348795434f
#define PAIR_SCALE   0.57735026918962584f

// ------------- device scratch -------------
__device__ __align__(16) float g_wall [DIM * NPROJ];
__device__ __align__(16) float g_proj [NT * NPROJ];
__device__ __align__(16) float g_qs   [NH * NT * 16];
__device__ __align__(16) float g_ks   [NH * NT * 16];
__device__ __align__(16) float g_vs   [NH * NT * 16];
__device__ __align__(16) float g_qpg  [NH * NT * 12];
__device__ __align__(16) float g_kpg  [NH * NT * 12];
__device__ __align__(16) float g_vpg  [NH * NT * 24];
__device__ __align__(16) float g_feats[(size_t)NT * FEAT];
__device__ __align__(16) float g_part [SPLITK * NT * DIM];

// ------------- pack weights -------------
__global__ __launch_bounds__(256) void pack_w(
    const float* __restrict__ Wq,  const float* __restrict__ Wk,
    const float* __restrict__ Wv,  const float* __restrict__ Wpq,
    const float* __restrict__ Wpk, const float* __restrict__ Wpv)
{
    int e = blockIdx.x * 256 + threadIdx.x;
    if (e >= DIM * NPROJ) return;
    int r = e / NPROJ, c = e % NPROJ;
    float v;
    if      (c < 192) v = Wq [r*192 + c];
    else if (c < 384) v = Wk [r*192 + (c-192)];
    else if (c < 576) v = Wv [r*192 + (c-384)];
    else if (c < 720) v = Wpq[r*144 + (c-576)];
    else if (c < 864) v = Wpk[r*144 + (c-720)];
    else              v = Wpv[r*288 + (c-864)];
    g_wall[e] = v;
}

// ------------- split-K SGEMM: 64x64 tile, TM=8 TN=4, 128 threads ----------
__global__ __launch_bounds__(128) void sgemm_sk(
    const float* __restrict__ A, const float* __restrict__ B,
    float* __restrict__ C, int M, int N, int K)
{
    __shared__ float As[16][64];
    __shared__ float Bs[16][68];
    const int tid = threadIdx.x;
    const int tx = tid & 15, ty = tid >> 4;
    const int row0 = blockIdx.y * 64, col0 = blockIdx.x * 64;
    const int kchunk = K / gridDim.z;
    const int kbeg = blockIdx.z * kchunk;

    float acc[8][4];
#pragma unroll
    for (int m = 0; m < 8; m++)
#pragma unroll
        for (int n = 0; n < 4; n++) acc[m][n] = 0.f;

    for (int k0 = kbeg; k0 < kbeg + kchunk; k0 += 16) {
        for (int e = tid; e < 256; e += 128) {
            int r = e >> 2, c4 = e & 3;
            float4 v = *reinterpret_cast<const float4*>(
                &A[(size_t)(row0+r)*K + k0 + c4*4]);
            As[c4*4+0][r] = v.x; As[c4*4+1][r] = v.y;
            As[c4*4+2][r] = v.z; As[c4*4+3][r] = v.w;
        }
        for (int e = tid; e < 256; e += 128) {
            int r = e >> 4, c4 = e & 15;
            *reinterpret_cast<float4*>(&Bs[r][c4*4]) =
                *reinterpret_cast<const float4*>(
                    &B[(size_t)(k0+r)*N + col0 + c4*4]);
        }
        __syncthreads();
#pragma unroll
        for (int kk = 0; kk < 16; kk++) {
            float a[8];
#pragma unroll
            for (int m = 0; m < 8; m++) a[m] = As[kk][ty*8 + m];
            float4 b = *reinterpret_cast<const float4*>(&Bs[kk][tx*4]);
#pragma unroll
            for (int m = 0; m < 8; m++) {
                acc[m][0] += a[m]*b.x; acc[m][1] += a[m]*b.y;
                acc[m][2] += a[m]*b.z; acc[m][3] += a[m]*b.w;
            }
        }
        __syncthreads();
    }
    float* Cz = C + (size_t)blockIdx.z * M * N;
#pragma unroll
    for (int m = 0; m < 8; m++) {
        int r = row0 + ty*8 + m;
        float4 v = make_float4(acc[m][0], acc[m][1], acc[m][2], acc[m][3]);
        *reinterpret_cast<float4*>(&Cz[(size_t)r*N + col0 + tx*4]) = v;
    }
}

// ------------- split-K reduce (+ output bias) -------------
__global__ __launch_bounds__(256) void reduce_k(
    float* __restrict__ out, const float* __restrict__ bout)
{
    int e = blockIdx.x * 256 + threadIdx.x;
    if (e >= NT * DIM) return;
    float s = 0.f;
#pragma unroll
    for (int z = 0; z < SPLITK; z++) s += g_part[(size_t)z*NT*DIM + e];
    out[e] = s + bout[e % DIM];
}

// ------------- relayout + rotate points to global frame -------------
__global__ __launch_bounds__(128) void relayout(
    const float* __restrict__ rot, const float* __restrict__ trans)
{
    const int i = blockIdx.x, t = threadIdx.x;
    __shared__ float R[9], tv[3];
    if (t < 9) R[t]  = rot[i*9 + t];
    if (t < 3) tv[t] = trans[i*3 + t];
    __syncthreads();
    const float* pr = g_proj + (size_t)i * NPROJ;
    for (int e = t; e < NH*16; e += 128) {
        int h = e/16, d = e%16;
        g_qs[((size_t)h*NT+i)*16+d] = pr[      h*16+d];
        g_ks[((size_t)h*NT+i)*16+d] = pr[192 + h*16+d];
        g_vs[((size_t)h*NT+i)*16+d] = pr[384 + h*16+d];
    }
    for (int e = t; e < NH*4; e += 128) {
        int h = e/4, p = e%4;
        const float* s = pr + 576 + h*12 + p*3;
        float x=s[0], y=s[1], z=s[2];
        float* o = g_qpg + ((size_t)h*NT+i)*12 + p*3;
        o[0]=R[0]*x+R[1]*y+R[2]*z+tv[0];
        o[1]=R[3]*x+R[4]*y+R[5]*z+tv[1];
        o[2]=R[6]*x+R[7]*y+R[8]*z+tv[2];
        s = pr + 720 + h*12 + p*3; x=s[0]; y=s[1]; z=s[2];
        o = g_kpg + ((size_t)h*NT+i)*12 + p*3;
        o[0]=R[0]*x+R[1]*y+R[2]*z+tv[0];
        o[1]=R[3]*x+R[4]*y+R[5]*z+tv[1];
        o[2]=R[6]*x+R[7]*y+R[8]*z+tv[2];
    }
    for (int e = t; e < NH*8; e += 128) {
        int h = e/8, p = e%8;
        const float* s = pr + 864 + h*24 + p*3;
        float x=s[0], y=s[1], z=s[2];
        float* o = g_vpg + ((size_t)h*NT+i)*24 + p*3;
        o[0]=R[0]*x+R[1]*y+R[2]*z+tv[0];
        o[1]=R[3]*x+R[4]*y+R[5]*z+tv[1];
        o[2]=R[6]*x+R[7]*y+R[8]*z+tv[2];
    }
}

// ------------- fused attention + pair-bias GEMM (full-width bias) ---------
#define PRS_OFF 0                    // [3][32][132]
#define ACC_OFF 12672                // [3][12][168]
#define PPS_OFF 18720                // [3][12] rows, stride 33
#define QSS_OFF 19908
#define QPS_OFF 20484
#define MST_OFF 20916
#define LST_OFF 20952
#define FAC_OFF 20988
#define RS_OFF  21024
#define TV_OFF  21051
#define WT_OFF  21060                // [12][132] transposed Wpb
#define BB_OFF  22644                // [12]
#define BT_OFF  22656                // [3][12] rows, stride 33
#define SMEM_FLOATS 23844

__global__ __launch_bounds__(384, 2) void attn_k(
    const float* __restrict__ pair, const float* __restrict__ rot,
    const float* __restrict__ trans, const float* __restrict__ pwts,
    const float* __restrict__ Wpb, const float* __restrict__ bpb)
{
    extern __shared__ float sm[];
    float* prs  = sm + PRS_OFF;
    float* accs = sm + ACC_OFF;
    float* pps  = sm + PPS_OFF;
    float* qss  = sm + QSS_OFF;
    float* qps  = sm + QPS_OFF;
    float* mst  = sm + MST_OFF;
    float* lst  = sm + LST_OFF;
    float* facs = sm + FAC_OFF;
    float* Rs   = sm + RS_OFF;
    float* tvs  = sm + TV_OFF;
    float* wTs  = sm + WT_OFF;
    float* bbs  = sm + BB_OFF;
    float* bts  = sm + BT_OFF;

    const int i0 = blockIdx.x * TI;
    const int t  = threadIdx.x;
    const int h  = t >> 5, lane = t & 31;

    // pair-accumulate roles
    const int hg = t & 1;
    const int jq = (t >> 1) & 1;
    const int cc = (t >> 2) & 31;
    const int qq = t >> 7;
    // scalar/point roles
    const bool has_sp = (t < 360);
    const int q2  = t % 3;
    const int u3  = t / 3;
    const int hh2 = u3 / 10;
    const int c2  = u3 % 10;
    const float* vbase;
    int vstride;
    if (c2 < 4) { vbase = g_vs  + (size_t)hh2*NT*16 + c2*4;     vstride = 16; }
    else        { vbase = g_vpg + (size_t)hh2*NT*24 + (c2-4)*4; vstride = 24; }
    // bias roles: ALL 384 threads: row = t>>2 (0..95), head-triple = t&3
    const int brow = t >> 2;
    const int bg   = t & 3;
    const int bq_  = brow >> 5, br_ = brow & 31;

    float4 pacc[6];
#pragma unroll
    for (int m = 0; m < 6; m++) pacc[m] = make_float4(0.f,0.f,0.f,0.f);
    float4 spacc = make_float4(0.f,0.f,0.f,0.f);

    for (int e = t; e < TI*NH*16;  e += 384) {
        int q = e / (NH*16), rem = e % (NH*16);
        qss[e] = g_qs[((size_t)(rem/16)*NT + i0 + q)*16 + rem%16];
    }
    for (int e = t; e < TI*NH*12;  e += 384) {
        int q = e / (NH*12), rem = e % (NH*12);
        qps[e] = g_qpg[((size_t)(rem/12)*NT + i0 + q)*12 + rem%12];
    }
    for (int e = t; e < NH*PD; e += 384)
        wTs[(e >> 7)*132 + (e & 127)] = Wpb[(e & 127)*12 + (e >> 7)];
    if (t < NH) bbs[t] = bpb[t];
    if (t < TI*NH) { mst[t] = -1e30f; lst[t] = 0.f; }
    if (t < TI*9)  Rs[t]  = rot[(i0 + t/9)*9 + t%9];
    if (t < TI*3)  tvs[t] = trans[(i0 + t/3)*3 + t%3];
    __syncthreads();

    float wv = pwts[h];
    float pwh = (wv > 20.f) ? wv : log1pf(expf(wv));
    const float pscale = -0.5f * POINT_SCALE * pwh;

    for (int jt = 0; jt < NTILE; jt++) {
        const int j0 = jt * 32;
        // ---- stage pair tiles (8 LDGs in flight) ----
#pragma unroll
        for (int u = 0; u < 8; u++) {
            int e = t + u*384;
            int q = e >> 10, rem = e & 1023;
            int r = rem >> 5, c = rem & 31;
            float4 v = *reinterpret_cast<const float4*>(
                pair + ((size_t)(i0+q)*NT + j0 + r)*PD + c*4);
            *reinterpret_cast<float4*>(&prs[(q*32 + r)*132 + c*4]) = v;
        }
        __syncthreads();
        // ---- K loads issued early: latency hides under bias ----
        const int j = j0 + lane;
        const float4* krp = reinterpret_cast<const float4*>(g_ks  + ((size_t)h*NT + j)*16);
        const float4* kpp = reinterpret_cast<const float4*>(g_kpg + ((size_t)h*NT + j)*12);
        float4 k0 = krp[0], k1 = krp[1], k2 = krp[2], k3 = krp[3];
        float4 p0 = kpp[0], p1 = kpp[1], p2 = kpp[2];
        // ---- fused pair-bias: ALL 384 threads (1 row x 3 heads each) ----
        {
            const float* w0 = wTs + (3*bg+0)*132;
            const float* w1 = wTs + (3*bg+1)*132;
            const float* w2 = wTs + (3*bg+2)*132;
            const float* prow = prs + brow*132;
            float b0 = 0.f, b1 = 0.f, b2 = 0.f;
#pragma unroll 8
            for (int k4 = 0; k4 < 32; k4++) {
                float4 v  = *reinterpret_cast<const float4*>(prow + k4*4);
                float4 wa = *reinterpret_cast<const float4*>(w0 + k4*4);
                float4 wb = *reinterpret_cast<const float4*>(w1 + k4*4);
                float4 wc = *reinterpret_cast<const float4*>(w2 + k4*4);
                b0 += v.x*wa.x + v.y*wa.y + v.z*wa.z + v.w*wa.w;
                b1 += v.x*wb.x + v.y*wb.y + v.z*wb.z + v.w*wb.w;
                b2 += v.x*wc.x + v.y*wc.y + v.z*wc.z + v.w*wc.w;
            }
            bts[(bq_*NH + 3*bg+0)*33 + br_] = (b0 + bbs[3*bg+0]) * PAIR_SCALE;
            bts[(bq_*NH + 3*bg+1)*33 + br_] = (b1 + bbs[3*bg+1]) * PAIR_SCALE;
            bts[(bq_*NH + 3*bg+2)*33 + br_] = (b2 + bbs[3*bg+2]) * PAIR_SCALE;
        }
        __syncthreads();
        // ---- logits: interleaved 3-q softmax chains ----
        {
            float s[TI];
#pragma unroll
            for (int q = 0; q < TI; q++) {
                const float4* qsv = reinterpret_cast<const float4*>(qss + (q*NH + h)*16);
                const float4* qpv = reinterpret_cast<const float4*>(qps + (q*NH + h)*12);
                float4 a0 = qsv[0], a1 = qsv[1], a2 = qsv[2], a3 = qsv[3];
                float sv = a0.x*k0.x + a0.y*k0.y + a0.z*k0.z + a0.w*k0.w
                         + a1.x*k1.x + a1.y*k1.y + a1.z*k1.z + a1.w*k1.w
                         + a2.x*k2.x + a2.y*k2.y + a2.z*k2.z + a2.w*k2.w
                         + a3.x*k3.x + a3.y*k3.y + a3.z*k3.z + a3.w*k3.w;
                sv *= SCALAR_SCALE;
                float4 b0 = qpv[0], b1 = qpv[1], b2 = qpv[2];
                float dx, dist = 0.f;
                dx = b0.x-p0.x; dist += dx*dx; dx = b0.y-p0.y; dist += dx*dx;
                dx = b0.z-p0.z; dist += dx*dx; dx = b0.w-p0.w; dist += dx*dx;
                dx = b1.x-p1.x; dist += dx*dx; dx = b1.y-p1.y; dist += dx*dx;
                dx = b1.z-p1.z; dist += dx*dx; dx = b1.w-p1.w; dist += dx*dx;
                dx = b2.x-p2.x; dist += dx*dx; dx = b2.y-p2.y; dist += dx*dx;
                dx = b2.z-p2.z; dist += dx*dx; dx = b2.w-p2.w; dist += dx*dx;
                sv += pscale * dist;
                sv += bts[(q*NH + h)*33 + lane];
                s[q] = sv;
            }
            float mx[TI];
#pragma unroll
            for (int q = 0; q < TI; q++) mx[q] = s[q];
#pragma unroll
            for (int o = 16; o; o >>= 1) {
#pragma unroll
                for (int q = 0; q < TI; q++)
                    mx[q] = fmaxf(mx[q], __shfl_xor_sync(~0u, mx[q], o));
            }
            float mold[TI], mnew[TI], ps[TI];
#pragma unroll
            for (int q = 0; q < TI; q++) {
                mold[q] = mst[q*NH + h];
                mnew[q] = fmaxf(mold[q], mx[q]);
                float p = __expf(s[q] - mnew[q]);
                pps[(q*NH + h)*33 + lane] = p;
                ps[q] = p;
            }
#pragma unroll
            for (int o = 16; o; o >>= 1) {
#pragma unroll
                for (int q = 0; q < TI; q++)
                    ps[q] += __shfl_xor_sync(~0u, ps[q], o);
            }
            if (lane == 0) {
#pragma unroll
                for (int q = 0; q < TI; q++) {
                    float f = __expf(mold[q] - mnew[q]);
                    facs[q*NH + h] = f;
                    lst[q*NH + h] = lst[q*NH + h]*f + ps[q];
                    mst[q*NH + h] = mnew[q];
                }
            }
        }
        __syncthreads();
        // ---- pair accumulate in registers ----
        {
            const float* fq = facs + qq*NH + hg*6;
            float f0=fq[0], f1=fq[1], f2=fq[2], f3=fq[3], f4=fq[4], f5=fq[5];
            pacc[0].x*=f0; pacc[0].y*=f0; pacc[0].z*=f0; pacc[0].w*=f0;
            pacc[1].x*=f1; pacc[1].y*=f1; pacc[1].z*=f1; pacc[1].w*=f1;
            pacc[2].x*=f2; pacc[2].y*=f2; pacc[2].z*=f2; pacc[2].w*=f2;
            pacc[3].x*=f3; pacc[3].y*=f3; pacc[3].z*=f3; pacc[3].w*=f3;
            pacc[4].x*=f4; pacc[4].y*=f4; pacc[4].z*=f4; pacc[4].w*=f4;
            pacc[5].x*=f5; pacc[5].y*=f5; pacc[5].z*=f5; pacc[5].w*=f5;
            const float* pbase = pps + (qq*NH + hg*6)*33 + jq*16;
            const float* prow  = prs + (qq*32 + jq*16)*132 + cc*4;
#pragma unroll
            for (int jj = 0; jj < 16; jj++) {
                float4 v = *reinterpret_cast<const float4*>(prow + jj*132);
                float pa = pbase[0*33+jj], pb = pbase[1*33+jj], pc = pbase[2*33+jj];
                float pd = pbase[3*33+jj], pe = pbase[4*33+jj], pf = pbase[5*33+jj];
                pacc[0].x += pa*v.x; pacc[0].y += pa*v.y; pacc[0].z += pa*v.z; pacc[0].w += pa*v.w;
                pacc[1].x += pb*v.x; pacc[1].y += pb*v.y; pacc[1].z += pb*v.z; pacc[1].w += pb*v.w;
                pacc[2].x += pc*v.x; pacc[2].y += pc*v.y; pacc[2].z += pc*v.z; pacc[2].w += pc*v.w;
                pacc[3].x += pd*v.x; pacc[3].y += pd*v.y; pacc[3].z += pd*v.z; pacc[3].w += pd*v.w;
                pacc[4].x += pe*v.x; pacc[4].y += pe*v.y; pacc[4].z += pe*v.z; pacc[4].w += pe*v.w;
                pacc[5].x += pf*v.x; pacc[5].y += pf*v.y; pacc[5].z += pf*v.z; pacc[5].w += pf*v.w;
            }
        }
        // ---- scalar/point accumulate ----
        if (has_sp) {
            float f = facs[q2*NH + hh2];
            spacc.x *= f; spacc.y *= f; spacc.z *= f; spacc.w *= f;
            const float* pph = pps + (q2*NH + hh2)*33;
            const float* src = vbase + (size_t)j0*vstride;
#pragma unroll 8
            for (int jv = 0; jv < 32; jv++) {
                float p = pph[jv];
                float4 v = *reinterpret_cast<const float4*>(src + (size_t)jv*vstride);
                spacc.x += p*v.x; spacc.y += p*v.y; spacc.z += p*v.z; spacc.w += p*v.w;
            }
        }
        __syncthreads();
    }

    // ---- merge register accumulators ----
    {
        int base = (qq*NH + hg*6)*168 + 40 + cc*4;
        if (jq == 0) {
#pragma unroll
            for (int m = 0; m < 6; m++)
                *reinterpret_cast<float4*>(accs + base + m*168) = pacc[m];
        }
        if (has_sp) {
            int off = (c2 < 4) ? c2*4 : 16 + (c2-4)*4;
            *reinterpret_cast<float4*>(accs + (q2*NH + hh2)*168 + off) = spacc;
        }
        __syncthreads();
        if (jq == 1) {
#pragma unroll
            for (int m = 0; m < 6; m++) {
                float4* p = reinterpret_cast<float4*>(accs + base + m*168);
                float4 a = *p;
                a.x += pacc[m].x; a.y += pacc[m].y; a.z += pacc[m].z; a.w += pacc[m].w;
                *p = a;
            }
        }
        __syncthreads();
    }

    // ---- finalize ----
    for (int e = t; e < TI*NH*16; e += 384) {
        int q = e / (NH*16), rem = e % (NH*16);
        int hh = rem/16, d = rem%16;
        g_feats[(size_t)(i0+q)*FEAT + hh*16 + d] =
            accs[(q*NH+hh)*168 + d] / lst[q*NH+hh];
    }
    for (int e = t; e < TI*NH*8; e += 384) {
        int q = e / (NH*8), rem = e % (NH*8);
        int hh = rem/8, p = rem%8;
        float inv = 1.f / lst[q*NH+hh];
        const float* R = Rs + q*9;
        const float* tv = tvs + q*3;
        const float* ac = accs + (q*NH+hh)*168 + 16 + p*3;
        float gx = ac[0]*inv - tv[0];
        float gy = ac[1]*inv - tv[1];
        float gz = ac[2]*inv - tv[2];
        float lx = R[0]*gx + R[3]*gy + R[6]*gz;
        float ly = R[1]*gx + R[4]*gy + R[7]*gz;
        float lz = R[2]*gx + R[5]*gy + R[8]*gz;
        float* fo = g_feats + (size_t)(i0+q)*FEAT;
        fo[192 + hh*24 + p*3 + 0] = lx;
        fo[192 + hh*24 + p*3 + 1] = ly;
        fo[192 + hh*24 + p*3 + 2] = lz;
        fo[480 + hh*8 + p] = sqrtf(lx*lx + ly*ly + lz*lz + 1e-8f);
    }
    for (int e = t; e < TI*NH*PD; e += 384) {
        int q = e / (NH*PD), rem = e % (NH*PD);
        int hh = rem/PD, d = rem%PD;
        g_feats[(size_t)(i0+q)*FEAT + 576 + hh*PD + d] =
            accs[(q*NH+hh)*168 + 40 + d] / lst[q*NH+hh];
    }
}

// ------------- launch -------------
extern "C" void kernel_launch(void* const* d_in, const int* in_sizes, int n_in,
                              void* d_out, int out_size)
{
    (void)in_sizes; (void)n_in; (void)out_size;
    const float* x     = (const float*)d_in[0];
    const float* pair  = (const float*)d_in[1];
    const float* rot   = (const float*)d_in[2];
    const float* trans = (const float*)d_in[3];
    const float* Wq    = (const float*)d_in[4];
    const float* Wk    = (const float*)d_in[5];
    const float* Wv    = (const float*)d_in[6];
    const float* Wpq   = (const float*)d_in[7];
    const float* Wpk   = (const float*)d_in[8];
    const float* Wpv   = (const float*)d_in[9];
    const float* Wpb   = (const float*)d_in[10];
    const float* bpb   = (const float*)d_in[11];
    const float* pwts  = (const float*)d_in[12];
    const float* Wout  = (const float*)d_in[13];
    const float* bout  = (const float*)d_in[14];
    float* out = (float*)d_out;

    cudaFuncSetAttribute(attn_k, cudaFuncAttributeMaxDynamicSharedMemorySize,
                         SMEM_FLOATS * 4);

    void *p_wall, *p_proj, *p_feats, *p_part;
    cudaGetSymbolAddress(&p_wall,  g_wall);
    cudaGetSymbolAddress(&p_proj,  g_proj);
    cudaGetSymbolAddress(&p_feats, g_feats);
    cudaGetSymbolAddress(&p_part,  g_part);

    pack_w<<<(DIM*NPROJ + 255)/256, 256>>>(Wq, Wk, Wv, Wpq, Wpk, Wpv);
    {
        dim3 g(NPROJ/64, NT/64, 1);
        sgemm_sk<<<g, 128>>>(x, (const float*)p_wall, (float*)p_proj,
                             NT, NPROJ, DIM);
    }
    relayout<<<NT, 128>>>(rot, trans);
    attn_k<<<NT/TI, 384, SMEM_FLOATS*4>>>(pair, rot, trans, pwts, Wpb, bpb);
    {
        dim3 g(DIM/64, NT/64, SPLITK);
        sgemm_sk<<<g, 128>>>((const float*)p_feats, Wout, (float*)p_part,
                             NT, DIM, FEAT);
    }
    reduce_k<<<(NT*DIM + 255)/256, 256>>>(out, bout);
}